// round 9
// baseline (speedup 1.0000x reference)
#include <cuda_runtime.h>
#include <cuda_bf16.h>
#include <cstdint>

// out = x @ W,  W = m + softplus(s) * mean_k(eps)
// Fused producer/consumer kernel, 144 co-resident CTAs, 512 threads each:
//   CTAs [32,144): 112 producers — work-steal 2-row chunks of W (MLP 20/thread),
//                  publish per-128-row chunk flags via red.release.
//   CTAs [0,32):   consumers — split x slice, then 128x256 tile GEMM
//                  (16 warps, 32x64 warp tiles), chunk-gated.

#define B_DIM 1024
#define IN_DIM 1024
#define OUT_DIM 1024
#define K_SAMPLES 100
#define PLANE ((IN_DIM * OUT_DIM) / 4)

#define N_CONS 32
#define N_PROD 112
#define GRID_TOTAL (N_CONS + N_PROD)
#define NTHREADS 512

__device__ __nv_bfloat16 d_xhi[B_DIM * IN_DIM];
__device__ __nv_bfloat16 d_xlo[B_DIM * IN_DIM];
__device__ __nv_bfloat16 d_whi[IN_DIM * OUT_DIM];   // [k][n]
__device__ __nv_bfloat16 d_wlo[IN_DIM * OUT_DIM];
// [0]=x rows (1024), [1..8]=W rows per 128-chunk, [15]=producer row counter
__device__ int g_flags[16];

// ---------------------------------------------------------------------------
__device__ __forceinline__ uint32_t smem_u32(const void* p) {
    uint32_t a;
    asm("{ .reg .u64 t; cvta.to.shared.u64 t, %1; cvt.u32.u64 %0, t; }"
        : "=r"(a) : "l"(p));
    return a;
}
__device__ __forceinline__ void cp16(uint32_t dst, const void* src) {
    asm volatile("cp.async.cg.shared.global [%0], [%1], 16;"
                 :: "r"(dst), "l"(__cvta_generic_to_global(src)) : "memory");
}
__device__ __forceinline__ void ldm4(uint32_t addr, uint32_t r[4]) {
    asm volatile("ldmatrix.sync.aligned.m8n8.x4.shared.b16 {%0,%1,%2,%3}, [%4];"
                 : "=r"(r[0]), "=r"(r[1]), "=r"(r[2]), "=r"(r[3]) : "r"(addr));
}
__device__ __forceinline__ void ldm4t(uint32_t addr, uint32_t r[4]) {
    asm volatile("ldmatrix.sync.aligned.m8n8.x4.trans.shared.b16 {%0,%1,%2,%3}, [%4];"
                 : "=r"(r[0]), "=r"(r[1]), "=r"(r[2]), "=r"(r[3]) : "r"(addr));
}
__device__ __forceinline__ void mma_bf16(float c[4], const uint32_t a[4],
                                         const uint32_t b[2]) {
    asm volatile(
        "mma.sync.aligned.m16n8k16.row.col.f32.bf16.bf16.f32 "
        "{%0,%1,%2,%3}, {%4,%5,%6,%7}, {%8,%9}, {%0,%1,%2,%3};"
        : "+f"(c[0]), "+f"(c[1]), "+f"(c[2]), "+f"(c[3])
        : "r"(a[0]), "r"(a[1]), "r"(a[2]), "r"(a[3]), "r"(b[0]), "r"(b[1]));
}
__device__ __forceinline__ int ld_acq(int* p) {
    int v;
    asm volatile("ld.acquire.gpu.global.s32 %0, [%1];"
                 : "=r"(v) : "l"(p) : "memory");
    return v;
}
__device__ __forceinline__ void red_rel_add(int* p, int v) {
    asm volatile("red.release.gpu.global.add.s32 [%0], %1;"
                 :: "l"(p), "r"(v) : "memory");
}
__device__ __forceinline__ void wait_flag_block(int idx, int target) {
    if (threadIdx.x == 0) {
        while (ld_acq(&g_flags[idx]) < target) __nanosleep(64);
    }
    __syncthreads();
}
__device__ __forceinline__ void split_store(__nv_bfloat16* hi, __nv_bfloat16* lo,
                                            int idx4, float4 v) {
    __nv_bfloat16 h0 = __float2bfloat16_rn(v.x);
    __nv_bfloat16 h1 = __float2bfloat16_rn(v.y);
    __nv_bfloat16 h2 = __float2bfloat16_rn(v.z);
    __nv_bfloat16 h3 = __float2bfloat16_rn(v.w);
    __nv_bfloat16 l0 = __float2bfloat16_rn(v.x - __bfloat162float(h0));
    __nv_bfloat16 l1 = __float2bfloat16_rn(v.y - __bfloat162float(h1));
    __nv_bfloat16 l2 = __float2bfloat16_rn(v.z - __bfloat162float(h2));
    __nv_bfloat16 l3 = __float2bfloat16_rn(v.w - __bfloat162float(h3));
    __nv_bfloat162* hp = reinterpret_cast<__nv_bfloat162*>(hi) + idx4 * 2;
    __nv_bfloat162* lp = reinterpret_cast<__nv_bfloat162*>(lo) + idx4 * 2;
    hp[0] = __nv_bfloat162(h0, h1);
    hp[1] = __nv_bfloat162(h2, h3);
    lp[0] = __nv_bfloat162(l0, l1);
    lp[1] = __nv_bfloat162(l2, l3);
}
#define ADD4(a, b) { (a).x += (b).x; (a).y += (b).y; (a).z += (b).z; (a).w += (b).w; }

__device__ __forceinline__ void finalize_w(int idx, float4 sv,
                                           const float4* wm, const float4* ws) {
    const float inv_k = 1.0f / (float)K_SAMPLES;
    float4 m4 = wm[idx];
    float4 s4 = ws[idx];
    float sp_x = fmaxf(s4.x, 0.f) + log1pf(expf(-fabsf(s4.x)));
    float sp_y = fmaxf(s4.y, 0.f) + log1pf(expf(-fabsf(s4.y)));
    float sp_z = fmaxf(s4.z, 0.f) + log1pf(expf(-fabsf(s4.z)));
    float sp_w = fmaxf(s4.w, 0.f) + log1pf(expf(-fabsf(s4.w)));
    float4 w4;
    w4.x = fmaf(sp_x, sv.x * inv_k, m4.x);
    w4.y = fmaf(sp_y, sv.y * inv_k, m4.y);
    w4.z = fmaf(sp_z, sv.z * inv_k, m4.z);
    w4.w = fmaf(sp_w, sv.w * inv_k, m4.w);
    split_store(d_whi, d_wlo, idx, w4);
}

// ---------------------------------------------------------------------------
// Producer: steals 2-row chunks; each thread = 1 element x 20 planes in flight
// ---------------------------------------------------------------------------
__device__ void producer(const float4* __restrict__ eps,
                         const float4* __restrict__ wm,
                         const float4* __restrict__ ws) {
    __shared__ int s_row;
    const int t = threadIdx.x;

    for (;;) {
        if (t == 0) s_row = atomicAdd(&g_flags[15], 2);
        __syncthreads();
        const int r2 = s_row;
        if (r2 >= IN_DIM) break;

        const int idx = (r2 + (t >> 8)) * 256 + (t & 255);
        const float4* p0 = eps + idx;
        float4 s = make_float4(0.f, 0.f, 0.f, 0.f);
#pragma unroll 1
        for (int k = 0; k < K_SAMPLES; k += 20) {
            float4 e[20];
#pragma unroll
            for (int u = 0; u < 20; u++) e[u] = p0[(k + u) * PLANE];
#pragma unroll
            for (int u = 0; u < 10; u++) ADD4(e[u], e[u + 10]);
#pragma unroll
            for (int u = 0; u < 5; u++) ADD4(e[u], e[u + 5]);
            ADD4(e[0], e[2]); ADD4(e[1], e[3]); ADD4(e[0], e[4]);
            ADD4(e[0], e[1]); ADD4(s, e[0]);
        }
        finalize_w(idx, s, wm, ws);

        __syncthreads();                  // both rows' stores complete
        if (t == 0) red_rel_add(&g_flags[1 + (r2 >> 7)], 2);
    }
}

// ---------------------------------------------------------------------------
// Consumer: 128x256 tile, 16 warps (4x4 grid, 32x64 warp tiles),
// BKT=32, 3-stage cp.async, chunk-gated. B-frags streamed per q.
// ---------------------------------------------------------------------------
#define BM 128
#define BN 256
#define BKT 32
#define NKT (IN_DIM / BKT)            // 32 (4 per chunk)
#define NSTAGE 3
#define RSA 80
#define RSB 528
#define OFF_AH 0
#define OFF_AL (BM * RSA)                      // 10240
#define OFF_BH (2 * BM * RSA)                  // 20480
#define OFF_BL (OFF_BH + BKT * RSB)            // 37376
#define STAGE_BYTES (OFF_BH + 2 * BKT * RSB)   // 54272
#define FUSED_SMEM (NSTAGE * STAGE_BYTES)      // 162816

__device__ __forceinline__ void load_stage(uint32_t st, int bm, int bn,
                                           int k0, int tid) {
    // A: hi+lo, 128 rows x 4 chunks x 2 = 1024 cp16 -> 2 per thread
#pragma unroll
    for (int i = 0; i < 2; i++) {
        const int c = tid + i * 512;
        const int mat = c >> 9;
        const int r = (c >> 2) & 127;
        const int ch = c & 3;
        const __nv_bfloat16* src = (mat ? d_xlo : d_xhi)
                                 + (bm + r) * IN_DIM + k0 + ch * 8;
        cp16(st + (mat ? OFF_AL : OFF_AH) + r * RSA + ch * 16, src);
    }
    // B: hi+lo, 32 rows x 32 chunks x 2 = 2048 cp16 -> 4 per thread
    {
        const int row = tid >> 4;
        const int ch = tid & 15;
        const __nv_bfloat16* sh = d_whi + (k0 + row) * OUT_DIM + bn;
        const __nv_bfloat16* sl = d_wlo + (k0 + row) * OUT_DIM + bn;
        cp16(st + OFF_BH + row * RSB + ch * 16,        sh + ch * 8);
        cp16(st + OFF_BH + row * RSB + (ch + 16) * 16, sh + (ch + 16) * 8);
        cp16(st + OFF_BL + row * RSB + ch * 16,        sl + ch * 8);
        cp16(st + OFF_BL + row * RSB + (ch + 16) * 16, sl + (ch + 16) * 8);
    }
}

__device__ void consumer(int cid, const float4* __restrict__ x,
                         float* __restrict__ out, char* smem) {
    const uint32_t sbase = smem_u32(smem);
    const int tid = threadIdx.x;
    const int lane = tid & 31;
    const int wid = tid >> 5;
    const int wm = wid & 3;          // 32-row group (0..3)
    const int wn = wid >> 2;         // 64-col group (0..3)

    const int bm = (cid >> 2) * BM;
    const int bn = (cid & 3) * BN;

    // ---- Phase 0: split x rows [cid*32, cid*32+32) ----
    {
        const int base = cid * 32 * 256;
#pragma unroll
        for (int i = 0; i < 16; i++) {
            const int idx = base + i * 512 + tid;
            split_store(d_xhi, d_xlo, idx, x[idx]);
        }
        __syncthreads();
        if (tid == 0) red_rel_add(&g_flags[0], 32);
    }

    float acc[2][8][4];
#pragma unroll
    for (int i = 0; i < 2; i++)
#pragma unroll
        for (int j = 0; j < 8; j++)
#pragma unroll
            for (int k = 0; k < 4; k++) acc[i][j][k] = 0.f;

    const int ar = lane & 15;
    const int ak = (lane >> 4) * 8;
    const int bkr = (lane & 7) + ((lane >> 3) & 1) * 8;
    const int bnc = (lane >> 4) * 8;

    wait_flag_block(0, B_DIM);        // all x split
    wait_flag_block(1, 128);          // W chunk 0 ready
    int ready = 0;

#pragma unroll
    for (int s = 0; s < NSTAGE - 1; s++) {
        load_stage(sbase + s * STAGE_BYTES, bm, bn, s * BKT, tid);
        asm volatile("cp.async.commit_group;" ::: "memory");
    }

#pragma unroll 1
    for (int t = 0; t < NKT; ++t) {
        if (t <= NKT - NSTAGE)
            asm volatile("cp.async.wait_group %0;" :: "n"(NSTAGE - 2) : "memory");
        else
            asm volatile("cp.async.wait_group 0;" ::: "memory");
        __syncthreads();

        if (t + NSTAGE - 1 < NKT) {
            const int c = (t + NSTAGE - 1) >> 2;
            if (c > ready) { wait_flag_block(1 + c, 128); ready = c; }
            load_stage(sbase + ((t + NSTAGE - 1) % NSTAGE) * STAGE_BYTES,
                       bm, bn, (t + NSTAGE - 1) * BKT, tid);
            asm volatile("cp.async.commit_group;" ::: "memory");
        }

        const uint32_t st = sbase + (t % NSTAGE) * STAGE_BYTES;

#pragma unroll
        for (int ks = 0; ks < 2; ks++) {
            uint32_t ah[2][4], al[2][4];
#pragma unroll
            for (int mh = 0; mh < 2; mh++) {
                const int row = wm * 32 + mh * 16 + ar;
                const uint32_t ad = st + OFF_AH + row * RSA + (ks * 16 + ak) * 2;
                ldm4(ad, ah[mh]);
                ldm4(ad + (OFF_AL - OFF_AH), al[mh]);
            }
#pragma unroll
            for (int q = 0; q < 4; q++) {
                const int krow = ks * 16 + bkr;
                const int ncol = wn * 64 + q * 16 + bnc;
                const uint32_t bd = st + OFF_BH + krow * RSB + ncol * 2;
                uint32_t bt[4], ct[4];
                ldm4t(bd, bt);
                ldm4t(bd + (OFF_BL - OFF_BH), ct);
                uint32_t b0[2] = {bt[0], bt[1]}, b1[2] = {bt[2], bt[3]};
                uint32_t c0[2] = {ct[0], ct[1]}, c1[2] = {ct[2], ct[3]};
#pragma unroll
                for (int mh = 0; mh < 2; mh++) {
                    mma_bf16(acc[mh][2 * q],     ah[mh], b0);
                    mma_bf16(acc[mh][2 * q + 1], ah[mh], b1);
                    mma_bf16(acc[mh][2 * q],     ah[mh], c0);
                    mma_bf16(acc[mh][2 * q + 1], ah[mh], c1);
                    mma_bf16(acc[mh][2 * q],     al[mh], b0);
                    mma_bf16(acc[mh][2 * q + 1], al[mh], b1);
                }
            }
        }
    }

    const int crow = lane >> 2;
    const int ccol = (lane & 3) * 2;
#pragma unroll
    for (int mh = 0; mh < 2; mh++) {
#pragma unroll
        for (int nf = 0; nf < 8; nf++) {
            const int row = bm + wm * 32 + mh * 16 + crow;
            const int col = bn + wn * 64 + nf * 8 + ccol;
            *reinterpret_cast<float2*>(&out[row * OUT_DIM + col]) =
                make_float2(acc[mh][nf][0], acc[mh][nf][1]);
            *reinterpret_cast<float2*>(&out[(row + 8) * OUT_DIM + col]) =
                make_float2(acc[mh][nf][2], acc[mh][nf][3]);
        }
    }
}

// ---------------------------------------------------------------------------
__global__ __launch_bounds__(NTHREADS, 1)
void fused_kernel(const float4* __restrict__ x, const float4* __restrict__ eps,
                  const float4* __restrict__ wm, const float4* __restrict__ ws,
                  float* __restrict__ out) {
    extern __shared__ char smem[];
    if (blockIdx.x < N_CONS)
        consumer(blockIdx.x, x, out, smem);
    else
        producer(eps, wm, ws);
}

extern "C" void kernel_launch(void* const* d_in, const int* in_sizes, int n_in,
                              void* d_out, int out_size) {
    const float* x   = (const float*)d_in[0];
    const float* eps = (const float*)d_in[1];
    const float* wm  = (const float*)d_in[2];
    const float* ws  = (const float*)d_in[3];
    float* out = (float*)d_out;

    void* fp = nullptr;
    cudaGetSymbolAddress(&fp, g_flags);
    cudaMemsetAsync(fp, 0, sizeof(int) * 16);

    cudaFuncSetAttribute(fused_kernel,
                         cudaFuncAttributeMaxDynamicSharedMemorySize,
                         FUSED_SMEM);
    fused_kernel<<<GRID_TOTAL, NTHREADS, FUSED_SMEM>>>(
        (const float4*)x, (const float4*)eps,
        (const float4*)wm, (const float4*)ws, out);
}

// round 10
// speedup vs baseline: 1.1213x; 1.1213x over previous
#include <cuda_runtime.h>
#include <cuda_bf16.h>
#include <cstdint>

// out = x @ W,  W = m + softplus(s) * mean_k(eps)
// Fused producer/consumer kernel, 144 co-resident CTAs, 1024 threads each:
//   CTAs [64,144): 80 producers — build W hi/lo bf16, 4 k-rows/iter,
//                  10-plane MLP per thread, per-128-row chunk flags.
//   CTAs [0,64):   consumers — split x slice, then 64x256 tile GEMM
//                  (32 warps, 16x32 warp tiles), chunk-gated.

#define B_DIM 1024
#define IN_DIM 1024
#define OUT_DIM 1024
#define K_SAMPLES 100
#define PLANE ((IN_DIM * OUT_DIM) / 4)

#define N_CONS 64
#define N_PROD 80
#define GRID_TOTAL (N_CONS + N_PROD)
#define NTHREADS 1024

__device__ __nv_bfloat16 d_xhi[B_DIM * IN_DIM];
__device__ __nv_bfloat16 d_xlo[B_DIM * IN_DIM];
__device__ __nv_bfloat16 d_whi[IN_DIM * OUT_DIM];   // [k][n]
__device__ __nv_bfloat16 d_wlo[IN_DIM * OUT_DIM];
__device__ int g_flags[16];  // [0]=x rows (1024), [1..8]=W rows per 128-chunk

// ---------------------------------------------------------------------------
__device__ __forceinline__ uint32_t smem_u32(const void* p) {
    uint32_t a;
    asm("{ .reg .u64 t; cvta.to.shared.u64 t, %1; cvt.u32.u64 %0, t; }"
        : "=r"(a) : "l"(p));
    return a;
}
__device__ __forceinline__ void cp16(uint32_t dst, const void* src) {
    asm volatile("cp.async.cg.shared.global [%0], [%1], 16;"
                 :: "r"(dst), "l"(__cvta_generic_to_global(src)) : "memory");
}
__device__ __forceinline__ void ldm4(uint32_t addr, uint32_t r[4]) {
    asm volatile("ldmatrix.sync.aligned.m8n8.x4.shared.b16 {%0,%1,%2,%3}, [%4];"
                 : "=r"(r[0]), "=r"(r[1]), "=r"(r[2]), "=r"(r[3]) : "r"(addr));
}
__device__ __forceinline__ void ldm4t(uint32_t addr, uint32_t r[4]) {
    asm volatile("ldmatrix.sync.aligned.m8n8.x4.trans.shared.b16 {%0,%1,%2,%3}, [%4];"
                 : "=r"(r[0]), "=r"(r[1]), "=r"(r[2]), "=r"(r[3]) : "r"(addr));
}
__device__ __forceinline__ void mma_bf16(float c[4], const uint32_t a[4],
                                         const uint32_t b[2]) {
    asm volatile(
        "mma.sync.aligned.m16n8k16.row.col.f32.bf16.bf16.f32 "
        "{%0,%1,%2,%3}, {%4,%5,%6,%7}, {%8,%9}, {%0,%1,%2,%3};"
        : "+f"(c[0]), "+f"(c[1]), "+f"(c[2]), "+f"(c[3])
        : "r"(a[0]), "r"(a[1]), "r"(a[2]), "r"(a[3]), "r"(b[0]), "r"(b[1]));
}
__device__ __forceinline__ int ld_acq(int* p) {
    int v;
    asm volatile("ld.acquire.gpu.global.s32 %0, [%1];"
                 : "=r"(v) : "l"(p) : "memory");
    return v;
}
__device__ __forceinline__ void red_rel_add(int* p, int v) {
    asm volatile("red.release.gpu.global.add.s32 [%0], %1;"
                 :: "l"(p), "r"(v) : "memory");
}
__device__ __forceinline__ void wait_flag_block(int idx, int target) {
    if (threadIdx.x == 0) {
        while (ld_acq(&g_flags[idx]) < target) __nanosleep(64);
    }
    __syncthreads();
}
__device__ __forceinline__ void split_store(__nv_bfloat16* hi, __nv_bfloat16* lo,
                                            int idx4, float4 v) {
    __nv_bfloat16 h0 = __float2bfloat16_rn(v.x);
    __nv_bfloat16 h1 = __float2bfloat16_rn(v.y);
    __nv_bfloat16 h2 = __float2bfloat16_rn(v.z);
    __nv_bfloat16 h3 = __float2bfloat16_rn(v.w);
    __nv_bfloat16 l0 = __float2bfloat16_rn(v.x - __bfloat162float(h0));
    __nv_bfloat16 l1 = __float2bfloat16_rn(v.y - __bfloat162float(h1));
    __nv_bfloat16 l2 = __float2bfloat16_rn(v.z - __bfloat162float(h2));
    __nv_bfloat16 l3 = __float2bfloat16_rn(v.w - __bfloat162float(h3));
    __nv_bfloat162* hp = reinterpret_cast<__nv_bfloat162*>(hi) + idx4 * 2;
    __nv_bfloat162* lp = reinterpret_cast<__nv_bfloat162*>(lo) + idx4 * 2;
    hp[0] = __nv_bfloat162(h0, h1);
    hp[1] = __nv_bfloat162(h2, h3);
    lp[0] = __nv_bfloat162(l0, l1);
    lp[1] = __nv_bfloat162(l2, l3);
}
#define ADD4(a, b) { (a).x += (b).x; (a).y += (b).y; (a).z += (b).z; (a).w += (b).w; }

__device__ __forceinline__ void finalize_w(int idx, float4 sv,
                                           const float4* wm, const float4* ws) {
    const float inv_k = 1.0f / (float)K_SAMPLES;
    float4 m4 = wm[idx];
    float4 s4 = ws[idx];
    float sp_x = fmaxf(s4.x, 0.f) + log1pf(expf(-fabsf(s4.x)));
    float sp_y = fmaxf(s4.y, 0.f) + log1pf(expf(-fabsf(s4.y)));
    float sp_z = fmaxf(s4.z, 0.f) + log1pf(expf(-fabsf(s4.z)));
    float sp_w = fmaxf(s4.w, 0.f) + log1pf(expf(-fabsf(s4.w)));
    float4 w4;
    w4.x = fmaf(sp_x, sv.x * inv_k, m4.x);
    w4.y = fmaf(sp_y, sv.y * inv_k, m4.y);
    w4.z = fmaf(sp_z, sv.z * inv_k, m4.z);
    w4.w = fmaf(sp_w, sv.w * inv_k, m4.w);
    split_store(d_whi, d_wlo, idx, w4);
}

// ---------------------------------------------------------------------------
// Producer: 4 k-rows per iteration; each thread = 1 element x 10 planes MLP
// ---------------------------------------------------------------------------
__device__ void producer(int p, const float4* __restrict__ eps,
                         const float4* __restrict__ wm,
                         const float4* __restrict__ ws) {
    const int t = threadIdx.x;

    for (int rr = 4 * p; rr < IN_DIM; rr += 4 * N_PROD) {
        const int idx = (rr + (t >> 8)) * 256 + (t & 255);
        const float4* p0 = eps + idx;
        float4 s = make_float4(0.f, 0.f, 0.f, 0.f);
#pragma unroll 1
        for (int k = 0; k < K_SAMPLES; k += 10) {
            float4 e[10];
#pragma unroll
            for (int u = 0; u < 10; u++) e[u] = p0[(k + u) * PLANE];
#pragma unroll
            for (int u = 0; u < 5; u++) ADD4(e[u], e[u + 5]);
            ADD4(e[0], e[2]); ADD4(e[1], e[3]); ADD4(e[0], e[4]);
            ADD4(e[0], e[1]); ADD4(s, e[0]);
        }
        finalize_w(idx, s, wm, ws);

        __syncthreads();                  // all 4 rows' stores done
        if (t == 0) red_rel_add(&g_flags[1 + (rr >> 7)], 4);
    }
}

// ---------------------------------------------------------------------------
// Consumer: 64x256 tile, 32 warps (4x8 grid, 16x32 warp tiles),
// BKT=32, 3-stage cp.async, chunk-gated.
// ---------------------------------------------------------------------------
#define BM 64
#define BN 256
#define BKT 32
#define NKT (IN_DIM / BKT)            // 32 (4 per chunk)
#define NSTAGE 3
#define RSA 80
#define RSB 528
#define OFF_AH 0
#define OFF_AL (BM * RSA)
#define OFF_BH (2 * BM * RSA)
#define OFF_BL (OFF_BH + BKT * RSB)
#define STAGE_BYTES (OFF_BH + 2 * BKT * RSB)   // 44032
#define FUSED_SMEM (NSTAGE * STAGE_BYTES)      // 132096

__device__ __forceinline__ void load_stage(uint32_t st, int bm, int bn,
                                           int k0, int tid) {
    // A: hi+lo, 64 rows x 4 chunks x 2 = 512 cp16 (threads 0-511)
    if (tid < 512) {
        const int mat = tid >> 8;             // 0 hi, 1 lo
        const int r = (tid >> 2) & 63;
        const int ch = tid & 3;
        const __nv_bfloat16* src = (mat ? d_xlo : d_xhi)
                                 + (bm + r) * IN_DIM + k0 + ch * 8;
        cp16(st + (mat ? OFF_AL : OFF_AH) + r * RSA + ch * 16, src);
    }
    // B: hi+lo, 32 rows x 32 chunks x 2 = 2048 cp16 -> 2 per thread
    {
        const int row = tid >> 5;             // 0..31
        const int ch = tid & 31;              // 0..31
        const __nv_bfloat16* sh = d_whi + (k0 + row) * OUT_DIM + bn;
        const __nv_bfloat16* sl = d_wlo + (k0 + row) * OUT_DIM + bn;
        cp16(st + OFF_BH + row * RSB + ch * 16, sh + ch * 8);
        cp16(st + OFF_BL + row * RSB + ch * 16, sl + ch * 8);
    }
}

__device__ void consumer(int cid, const float4* __restrict__ x,
                         float* __restrict__ out, char* smem) {
    const uint32_t sbase = smem_u32(smem);
    const int tid = threadIdx.x;
    const int lane = tid & 31;
    const int wid = tid >> 5;            // 0..31
    const int wm = wid & 3;              // 16-row group (0..3)
    const int wn = wid >> 2;             // 32-col group (0..7)

    const int bm = (cid >> 2) * BM;
    const int bn = (cid & 3) * BN;

    // ---- Phase 0: split x rows [cid*16, cid*16+16) ----
    {
        const int base = cid * 16 * 256;
#pragma unroll
        for (int i = 0; i < 4; i++) {
            const int idx = base + i * 1024 + tid;
            split_store(d_xhi, d_xlo, idx, x[idx]);
        }
        __syncthreads();
        if (tid == 0) red_rel_add(&g_flags[0], 16);
    }

    float acc[4][4];
#pragma unroll
    for (int j = 0; j < 4; j++)
#pragma unroll
        for (int k = 0; k < 4; k++) acc[j][k] = 0.f;

    const int ar = lane & 15;
    const int ak = (lane >> 4) * 8;
    const int bkr = (lane & 7) + ((lane >> 3) & 1) * 8;
    const int bnc = (lane >> 4) * 8;

    wait_flag_block(0, B_DIM);        // all x split
    wait_flag_block(1, 128);          // W chunk 0 ready
    int ready = 0;

#pragma unroll
    for (int s = 0; s < NSTAGE - 1; s++) {
        load_stage(sbase + s * STAGE_BYTES, bm, bn, s * BKT, tid);
        asm volatile("cp.async.commit_group;" ::: "memory");
    }

#pragma unroll 1
    for (int t = 0; t < NKT; ++t) {
        if (t <= NKT - NSTAGE)
            asm volatile("cp.async.wait_group %0;" :: "n"(NSTAGE - 2) : "memory");
        else
            asm volatile("cp.async.wait_group 0;" ::: "memory");
        __syncthreads();

        if (t + NSTAGE - 1 < NKT) {
            const int c = (t + NSTAGE - 1) >> 2;
            if (c > ready) { wait_flag_block(1 + c, 128); ready = c; }
            load_stage(sbase + ((t + NSTAGE - 1) % NSTAGE) * STAGE_BYTES,
                       bm, bn, (t + NSTAGE - 1) * BKT, tid);
            asm volatile("cp.async.commit_group;" ::: "memory");
        }

        const uint32_t st = sbase + (t % NSTAGE) * STAGE_BYTES;

#pragma unroll
        for (int ks = 0; ks < 2; ks++) {
            uint32_t ah[4], al[4], bh[4][2], bl[4][2];
            {
                const int row = wm * 16 + ar;
                const uint32_t ad = st + OFF_AH + row * RSA + (ks * 16 + ak) * 2;
                ldm4(ad, ah);
                ldm4(ad + (OFF_AL - OFF_AH), al);
            }
#pragma unroll
            for (int q = 0; q < 2; q++) {
                const int krow = ks * 16 + bkr;
                const int ncol = wn * 32 + q * 16 + bnc;
                const uint32_t bd = st + OFF_BH + krow * RSB + ncol * 2;
                uint32_t tmp[4];
                ldm4t(bd, tmp);
                bh[2 * q][0] = tmp[0]; bh[2 * q][1] = tmp[1];
                bh[2 * q + 1][0] = tmp[2]; bh[2 * q + 1][1] = tmp[3];
                ldm4t(bd + (OFF_BL - OFF_BH), tmp);
                bl[2 * q][0] = tmp[0]; bl[2 * q][1] = tmp[1];
                bl[2 * q + 1][0] = tmp[2]; bl[2 * q + 1][1] = tmp[3];
            }
#pragma unroll
            for (int nf = 0; nf < 4; nf++) {
                mma_bf16(acc[nf], ah, bh[nf]);
                mma_bf16(acc[nf], ah, bl[nf]);
                mma_bf16(acc[nf], al, bh[nf]);
            }
        }
    }

    const int crow = lane >> 2;
    const int ccol = (lane & 3) * 2;
#pragma unroll
    for (int nf = 0; nf < 4; nf++) {
        const int row = bm + wm * 16 + crow;
        const int col = bn + wn * 32 + nf * 8 + ccol;
        *reinterpret_cast<float2*>(&out[row * OUT_DIM + col]) =
            make_float2(acc[nf][0], acc[nf][1]);
        *reinterpret_cast<float2*>(&out[(row + 8) * OUT_DIM + col]) =
            make_float2(acc[nf][2], acc[nf][3]);
    }
}

// ---------------------------------------------------------------------------
__global__ __launch_bounds__(NTHREADS, 1)
void fused_kernel(const float4* __restrict__ x, const float4* __restrict__ eps,
                  const float4* __restrict__ wm, const float4* __restrict__ ws,
                  float* __restrict__ out) {
    extern __shared__ char smem[];
    if (blockIdx.x < N_CONS)
        consumer(blockIdx.x, x, out, smem);
    else
        producer(blockIdx.x - N_CONS, eps, wm, ws);
}

extern "C" void kernel_launch(void* const* d_in, const int* in_sizes, int n_in,
                              void* d_out, int out_size) {
    const float* x   = (const float*)d_in[0];
    const float* eps = (const float*)d_in[1];
    const float* wm  = (const float*)d_in[2];
    const float* ws  = (const float*)d_in[3];
    float* out = (float*)d_out;

    void* fp = nullptr;
    cudaGetSymbolAddress(&fp, g_flags);
    cudaMemsetAsync(fp, 0, sizeof(int) * 16);

    cudaFuncSetAttribute(fused_kernel,
                         cudaFuncAttributeMaxDynamicSharedMemorySize,
                         FUSED_SMEM);
    fused_kernel<<<GRID_TOTAL, NTHREADS, FUSED_SMEM>>>(
        (const float4*)x, (const float4*)eps,
        (const float4*)wm, (const float4*)ws, out);
}

// round 13
// speedup vs baseline: 1.2869x; 1.1477x over previous
#include <cuda_runtime.h>
#include <cuda_bf16.h>
#include <cstdint>

// out = x @ W,  W = m + softplus(s) * mean_k(eps)
// 144 CTAs x 1024 threads, warp-specialized halves:
//   CTAs [0,128): lower 512 thr = consumer (64x128 tile GEMM), upper 512 = producer
//   CTAs [128,144): both halves producers
// Producers work-steal 1 W-row at a time (256 cols x 2 k-halves of 50 planes,
// combined via smem), publish per-128-row chunk flags. 160 streaming halves
// put every SM on the HBM path (per-SM streaming cap ~58GB/s, chip cap ~6.3TB/s).

#define B_DIM 1024
#define IN_DIM 1024
#define OUT_DIM 1024
#define K_SAMPLES 100
#define PLANE ((IN_DIM * OUT_DIM) / 4)

#define N_CONS 128            // consumer halves (CTAs 0..127, lower half)
#define GRID_TOTAL 144
#define NTHREADS 1024

__device__ __nv_bfloat16 d_xhi[B_DIM * IN_DIM];
__device__ __nv_bfloat16 d_xlo[B_DIM * IN_DIM];
__device__ __nv_bfloat16 d_whi[IN_DIM * OUT_DIM];   // [k][n]
__device__ __nv_bfloat16 d_wlo[IN_DIM * OUT_DIM];
// [0]=x rows (1024), [1..8]=W rows per 128-chunk, [15]=row steal counter
__device__ int g_flags[16];

// ---------------------------------------------------------------------------
__device__ __forceinline__ uint32_t smem_u32(const void* p) {
    uint32_t a;
    asm("{ .reg .u64 t; cvta.to.shared.u64 t, %1; cvt.u32.u64 %0, t; }"
        : "=r"(a) : "l"(p));
    return a;
}
__device__ __forceinline__ void barx(int id) {
    asm volatile("bar.sync %0, 512;" :: "r"(id) : "memory");
}
__device__ __forceinline__ void cp16(uint32_t dst, const void* src) {
    asm volatile("cp.async.cg.shared.global [%0], [%1], 16;"
                 :: "r"(dst), "l"(__cvta_generic_to_global(src)) : "memory");
}
__device__ __forceinline__ void ldm4(uint32_t addr, uint32_t r[4]) {
    asm volatile("ldmatrix.sync.aligned.m8n8.x4.shared.b16 {%0,%1,%2,%3}, [%4];"
                 : "=r"(r[0]), "=r"(r[1]), "=r"(r[2]), "=r"(r[3]) : "r"(addr));
}
__device__ __forceinline__ void ldm4t(uint32_t addr, uint32_t r[4]) {
    asm volatile("ldmatrix.sync.aligned.m8n8.x4.trans.shared.b16 {%0,%1,%2,%3}, [%4];"
                 : "=r"(r[0]), "=r"(r[1]), "=r"(r[2]), "=r"(r[3]) : "r"(addr));
}
__device__ __forceinline__ void mma_bf16(float c[4], const uint32_t a[4],
                                         const uint32_t b[2]) {
    asm volatile(
        "mma.sync.aligned.m16n8k16.row.col.f32.bf16.bf16.f32 "
        "{%0,%1,%2,%3}, {%4,%5,%6,%7}, {%8,%9}, {%0,%1,%2,%3};"
        : "+f"(c[0]), "+f"(c[1]), "+f"(c[2]), "+f"(c[3])
        : "r"(a[0]), "r"(a[1]), "r"(a[2]), "r"(a[3]), "r"(b[0]), "r"(b[1]));
}
__device__ __forceinline__ int ld_acq(int* p) {
    int v;
    asm volatile("ld.acquire.gpu.global.s32 %0, [%1];"
                 : "=r"(v) : "l"(p) : "memory");
    return v;
}
__device__ __forceinline__ void red_rel_add(int* p, int v) {
    asm volatile("red.release.gpu.global.add.s32 [%0], %1;"
                 :: "l"(p), "r"(v) : "memory");
}
__device__ __forceinline__ void split_store(__nv_bfloat16* hi, __nv_bfloat16* lo,
                                            int idx4, float4 v) {
    __nv_bfloat16 h0 = __float2bfloat16_rn(v.x);
    __nv_bfloat16 h1 = __float2bfloat16_rn(v.y);
    __nv_bfloat16 h2 = __float2bfloat16_rn(v.z);
    __nv_bfloat16 h3 = __float2bfloat16_rn(v.w);
    __nv_bfloat16 l0 = __float2bfloat16_rn(v.x - __bfloat162float(h0));
    __nv_bfloat16 l1 = __float2bfloat16_rn(v.y - __bfloat162float(h1));
    __nv_bfloat16 l2 = __float2bfloat16_rn(v.z - __bfloat162float(h2));
    __nv_bfloat16 l3 = __float2bfloat16_rn(v.w - __bfloat162float(h3));
    __nv_bfloat162* hp = reinterpret_cast<__nv_bfloat162*>(hi) + idx4 * 2;
    __nv_bfloat162* lp = reinterpret_cast<__nv_bfloat162*>(lo) + idx4 * 2;
    hp[0] = __nv_bfloat162(h0, h1);
    hp[1] = __nv_bfloat162(h2, h3);
    lp[0] = __nv_bfloat162(l0, l1);
    lp[1] = __nv_bfloat162(l2, l3);
}
#define ADD4(a, b) { (a).x += (b).x; (a).y += (b).y; (a).z += (b).z; (a).w += (b).w; }

__device__ __forceinline__ void finalize_w(int idx, float4 sv,
                                           const float4* wm, const float4* ws) {
    const float inv_k = 1.0f / (float)K_SAMPLES;
    float4 m4 = wm[idx];
    float4 s4 = ws[idx];
    float sp_x = fmaxf(s4.x, 0.f) + log1pf(expf(-fabsf(s4.x)));
    float sp_y = fmaxf(s4.y, 0.f) + log1pf(expf(-fabsf(s4.y)));
    float sp_z = fmaxf(s4.z, 0.f) + log1pf(expf(-fabsf(s4.z)));
    float sp_w = fmaxf(s4.w, 0.f) + log1pf(expf(-fabsf(s4.w)));
    float4 w4;
    w4.x = fmaf(sp_x, sv.x * inv_k, m4.x);
    w4.y = fmaf(sp_y, sv.y * inv_k, m4.y);
    w4.z = fmaf(sp_z, sv.z * inv_k, m4.z);
    w4.w = fmaf(sp_w, sv.w * inv_k, m4.w);
    split_store(d_whi, d_wlo, idx, w4);
}

// Static shared for producer halves (separate from dynamic consumer smem)
__shared__ int    s_row[2];
__shared__ float4 s_part[2][256];

// ---------------------------------------------------------------------------
// Producer half: steal 1 W-row; 512 thr = 256 cols x 2 k-halves (50 planes ea)
// ---------------------------------------------------------------------------
__device__ void producer_half(int slot, int barid,
                              const float4* __restrict__ eps,
                              const float4* __restrict__ wm,
                              const float4* __restrict__ ws) {
    const int t = threadIdx.x & 511;
    const int col = t & 255;
    const int kh = t >> 8;              // warps 0-7: kh=0, warps 8-15: kh=1

    for (;;) {
        if (t == 0) s_row[slot] = atomicAdd(&g_flags[15], 1);
        barx(barid);
        const int r = s_row[slot];
        if (r >= IN_DIM) break;

        const float4* p0 = eps + (kh * 50) * PLANE + r * 256 + col;
        float4 s = make_float4(0.f, 0.f, 0.f, 0.f);
#pragma unroll 1
        for (int k = 0; k < 50; k += 10) {
            float4 e[10];
#pragma unroll
            for (int u = 0; u < 10; u++) e[u] = p0[(k + u) * PLANE];
#pragma unroll
            for (int u = 0; u < 5; u++) ADD4(e[u], e[u + 5]);
            ADD4(e[0], e[2]); ADD4(e[1], e[3]); ADD4(e[0], e[4]);
            ADD4(e[0], e[1]); ADD4(s, e[0]);
        }
        if (kh) s_part[slot][col] = s;
        barx(barid);
        if (!kh) {
            float4 sp = s_part[slot][col];
            ADD4(s, sp);
            finalize_w(r * 256 + col, s, wm, ws);
        }
        barx(barid);
        if (t == 0) red_rel_add(&g_flags[1 + (r >> 7)], 1);
    }
}

// ---------------------------------------------------------------------------
// Consumer half: 64x128 tile, 16 warps (4x4 grid, 16x32 warp tiles),
// BKT=32, 3-stage cp.async, chunk-gated. Threads 0-511, barrier id 1.
// ---------------------------------------------------------------------------
#define BM 64
#define BN 128
#define BKT 32
#define NKT (IN_DIM / BKT)            // 32 (4 per chunk)
#define NSTAGE 3
#define RSA 80
#define RSB 272
#define OFF_AH 0
#define OFF_AL (BM * RSA)                      // 5120
#define OFF_BH (2 * BM * RSA)                  // 10240
#define OFF_BL (OFF_BH + BKT * RSB)            // 18944
#define STAGE_BYTES (OFF_BH + 2 * BKT * RSB)   // 27648
#define FUSED_SMEM (NSTAGE * STAGE_BYTES)      // 82944

__device__ __forceinline__ void wait_flag_cons(int idx, int target) {
    if (threadIdx.x == 0) {
        while (ld_acq(&g_flags[idx]) < target) __nanosleep(64);
    }
    barx(1);
}

__device__ __forceinline__ void load_stage(uint32_t st, int bm, int bn,
                                           int k0, int tid) {
    {   // A: hi+lo, 64 rows x 4 chunks x 2 = 512 cp16, one per thread
        const int mat = tid >> 8;
        const int r = (tid >> 2) & 63;
        const int ch = tid & 3;
        const __nv_bfloat16* src = (mat ? d_xlo : d_xhi)
                                 + (bm + r) * IN_DIM + k0 + ch * 8;
        cp16(st + (mat ? OFF_AL : OFF_AH) + r * RSA + ch * 16, src);
    }
    {   // B: hi+lo, 32 rows x 16 chunks x 2 = 1024 cp16, two per thread
        const int row = tid >> 4;             // 0..31
        const int ch = tid & 15;              // 0..15
        const __nv_bfloat16* sh = d_whi + (k0 + row) * OUT_DIM + bn;
        const __nv_bfloat16* sl = d_wlo + (k0 + row) * OUT_DIM + bn;
        cp16(st + OFF_BH + row * RSB + ch * 16, sh + ch * 8);
        cp16(st + OFF_BL + row * RSB + ch * 16, sl + ch * 8);
    }
}

__device__ void consumer(int cid, const float4* __restrict__ x,
                         float* __restrict__ out, char* smem) {
    const uint32_t sbase = smem_u32(smem);
    const int tid = threadIdx.x;          // 0..511
    const int lane = tid & 31;
    const int wid = tid >> 5;             // 0..15
    const int wm = wid & 3;               // 16-row group
    const int wn = wid >> 2;              // 32-col group

    const int bm = (cid >> 3) * BM;       // 16 m-tiles
    const int bn = (cid & 7) * BN;        // 8 n-tiles

    // Phase 0: split x rows [cid*8, cid*8+8)
    {
        const int base = cid * 8 * 256;
#pragma unroll
        for (int i = 0; i < 4; i++) {
            const int idx = base + i * 512 + tid;
            split_store(d_xhi, d_xlo, idx, x[idx]);
        }
        barx(1);
        if (tid == 0) red_rel_add(&g_flags[0], 8);
    }

    float acc[4][4];
#pragma unroll
    for (int j = 0; j < 4; j++)
#pragma unroll
        for (int k = 0; k < 4; k++) acc[j][k] = 0.f;

    const int ar = lane & 15;
    const int ak = (lane >> 4) * 8;
    const int bkr = (lane & 7) + ((lane >> 3) & 1) * 8;
    const int bnc = (lane >> 4) * 8;

    wait_flag_cons(0, B_DIM);
    wait_flag_cons(1, 128);
    int ready = 0;

#pragma unroll
    for (int s = 0; s < NSTAGE - 1; s++) {
        load_stage(sbase + s * STAGE_BYTES, bm, bn, s * BKT, tid);
        asm volatile("cp.async.commit_group;" ::: "memory");
    }

#pragma unroll 1
    for (int t = 0; t < NKT; ++t) {
        if (t <= NKT - NSTAGE)
            asm volatile("cp.async.wait_group %0;" :: "n"(NSTAGE - 2) : "memory");
        else
            asm volatile("cp.async.wait_group 0;" ::: "memory");
        barx(1);

        if (t + NSTAGE - 1 < NKT) {
            const int c = (t + NSTAGE - 1) >> 2;
            if (c > ready) { wait_flag_cons(1 + c, 128); ready = c; }
            load_stage(sbase + ((t + NSTAGE - 1) % NSTAGE) * STAGE_BYTES,
                       bm, bn, (t + NSTAGE - 1) * BKT, tid);
            asm volatile("cp.async.commit_group;" ::: "memory");
        }

        const uint32_t st = sbase + (t % NSTAGE) * STAGE_BYTES;

#pragma unroll
        for (int ks = 0; ks < 2; ks++) {
            uint32_t ah[4], al[4], bh[4][2], bl[4][2];
            {
                const int row = wm * 16 + ar;
                const uint32_t ad = st + OFF_AH + row * RSA + (ks * 16 + ak) * 2;
                ldm4(ad, ah);
                ldm4(ad + (OFF_AL - OFF_AH), al);
            }
#pragma unroll
            for (int q = 0; q < 2; q++) {
                const int krow = ks * 16 + bkr;
                const int ncol = wn * 32 + q * 16 + bnc;
                const uint32_t bd = st + OFF_BH + krow * RSB + ncol * 2;
                uint32_t tmp[4];
                ldm4t(bd, tmp);
                bh[2 * q][0] = tmp[0]; bh[2 * q][1] = tmp[1];
                bh[2 * q + 1][0] = tmp[2]; bh[2 * q + 1][1] = tmp[3];
                ldm4t(bd + (OFF_BL - OFF_BH), tmp);
                bl[2 * q][0] = tmp[0]; bl[2 * q][1] = tmp[1];
                bl[2 * q + 1][0] = tmp[2]; bl[2 * q + 1][1] = tmp[3];
            }
#pragma unroll
            for (int nf = 0; nf < 4; nf++) {
                mma_bf16(acc[nf], ah, bh[nf]);
                mma_bf16(acc[nf], ah, bl[nf]);
                mma_bf16(acc[nf], al, bh[nf]);
            }
        }
        barx(1);
    }

    const int crow = lane >> 2;
    const int ccol = (lane & 3) * 2;
#pragma unroll
    for (int nf = 0; nf < 4; nf++) {
        const int row = bm + wm * 16 + crow;
        const int col = bn + wn * 32 + nf * 8 + ccol;
        *reinterpret_cast<float2*>(&out[row * OUT_DIM + col]) =
            make_float2(acc[nf][0], acc[nf][1]);
        *reinterpret_cast<float2*>(&out[(row + 8) * OUT_DIM + col]) =
            make_float2(acc[nf][2], acc[nf][3]);
    }
}

// ---------------------------------------------------------------------------
__global__ __launch_bounds__(NTHREADS, 1)
void fused_kernel(const float4* __restrict__ x, const float4* __restrict__ eps,
                  const float4* __restrict__ wm, const float4* __restrict__ ws,
                  float* __restrict__ out) {
    extern __shared__ char smem[];
    const int half = threadIdx.x >> 9;      // 0 lower, 1 upper
    if (blockIdx.x < N_CONS && half == 0)
        consumer(blockIdx.x, x, out, smem);
    else
        producer_half(half, half + 1, eps, wm, ws);
}

extern "C" void kernel_launch(void* const* d_in, const int* in_sizes, int n_in,
                              void* d_out, int out_size) {
    const float* x   = (const float*)d_in[0];
    const float* eps = (const float*)d_in[1];
    const float* wm  = (const float*)d_in[2];
    const float* ws  = (const float*)d_in[3];
    float* out = (float*)d_out;

    void* fp = nullptr;
    cudaGetSymbolAddress(&fp, g_flags);
    cudaMemsetAsync(fp, 0, sizeof(int) * 16);

    cudaFuncSetAttribute(fused_kernel,
                         cudaFuncAttributeMaxDynamicSharedMemorySize,
                         FUSED_SMEM);
    fused_kernel<<<GRID_TOTAL, NTHREADS, FUSED_SMEM>>>(
        (const float4*)x, (const float4*)eps,
        (const float4*)wm, (const float4*)ws, out);
}